// round 12
// baseline (speedup 1.0000x reference)
#include <cuda_runtime.h>
#include <cstdint>

// Dense 2D spatial transformer (bilinear warp, zero-padded border).
// R11: software-pipelined vertical strips. Block = 256 cols x 16 rows,
// processed as 4 groups of 4 rows. Flow loads for group g+1 are issued
// (register double-buffer) before group g's gathers are consumed, hiding the
// flow-load latency and halving the exposed serial chain per iteration.
// Warp gather footprint stays 32 consecutive columns (R9 result).
//
// input1: [1,1,4096,4096] f32 image
// input2: [1,2,4096,4096] f32 flow (plane 0 = dH, plane 1 = dW)
// out:    [1,1,4096,4096] f32
//
// Reference semantics (padded coords in [0,4097], zero border):
//   H_up = flow_h + h + 1 ; W_up = flow_w + w + 1
//   hf = clip(floor(H_up),0,4097); hc = clip(hf+1,0,4097); same for w
//   dH = hc - H_up; dW = wc - W_up   (weights from CLIPPED coords)
//   out = v00*dW*dH + v10*dW*(1-dH) + v01*(1-dW)*dH + v11*(1-dW)*(1-dH)

#define H_DIM 4096
#define W_DIM 4096
#define HP_MAX 4097
#define RPT 4      // rows per pipeline stage
#define NITER 4    // stages per block -> block covers 16 rows

__device__ __forceinline__ float fetch_padded(const float* __restrict__ img, int h, int w) {
    bool in = ((unsigned)(h - 1) < (unsigned)H_DIM) & ((unsigned)(w - 1) < (unsigned)W_DIM);
    int idx = ((h - 1) << 12) + (w - 1);
    return in ? __ldg(img + idx) : 0.0f;
}

__global__ void __launch_bounds__(256, 4)
dense_warp_kernel(const float* __restrict__ img,
                  const float* __restrict__ flowH,
                  const float* __restrict__ flowW,
                  float* __restrict__ out) {
    const int w  = (blockIdx.x << 8) + threadIdx.x;
    const int h0 = blockIdx.y * (RPT * NITER);
    const int base0 = (h0 << 12) + w;        // element index of (h0, w)

    const float wp1 = (float)(w + 1);

    float fhb[2][RPT], fwb[2][RPT];

    // prologue: flow for group 0
    #pragma unroll
    for (int k = 0; k < RPT; k++) {
        fhb[0][k] = __ldg(flowH + base0 + (k << 12));
        fwb[0][k] = __ldg(flowW + base0 + (k << 12));
    }

    #pragma unroll
    for (int g = 0; g < NITER; g++) {
        const int cur = g & 1;
        const int nxt = cur ^ 1;
        const int gbase = base0 + ((g * RPT) << 12);

        // prefetch flow for group g+1 (in flight during this group's gathers)
        if (g + 1 < NITER) {
            const int nbase = base0 + (((g + 1) * RPT) << 12);
            #pragma unroll
            for (int k = 0; k < RPT; k++) {
                fhb[nxt][k] = __ldg(flowH + nbase + (k << 12));
                fwb[nxt][k] = __ldg(flowW + nbase + (k << 12));
            }
        }

        const float hp1 = (float)(h0 + g * RPT + 1);

        float v00[RPT], v01[RPT], v10[RPT], v11[RPT];
        float dH[RPT], dW[RPT];

        // phase 1: indices + issue all 16 gathers
        #pragma unroll
        for (int k = 0; k < RPT; k++) {
            float Hu = fhb[cur][k] + hp1 + (float)k;
            float Wu = fwb[cur][k] + wp1;

            float fhf = floorf(Hu);
            float fwf = floorf(Wu);
            int hf = (int)fhf;
            int wf = (int)fwf;

            if (((unsigned)(hf - 1) <= 4094u) & ((unsigned)(wf - 1) <= 4094u)) {
                // interior fast path: one base index, immediate offsets
                dH[k] = (fhf + 1.0f) - Hu;
                dW[k] = (fwf + 1.0f) - Wu;
                int idx = (hf << 12) + wf - (W_DIM + 1);   // (hf-1)*4096 + (wf-1)
                v00[k] = __ldg(img + idx);
                v01[k] = __ldg(img + idx + 1);
                v10[k] = __ldg(img + idx + W_DIM);
                v11[k] = __ldg(img + idx + W_DIM + 1);
            } else {
                int hc = hf + 1, wc = wf + 1;
                int hfc = min(max(hf, 0), HP_MAX);
                int hcc = min(max(hc, 0), HP_MAX);
                int wfc = min(max(wf, 0), HP_MAX);
                int wcc = min(max(wc, 0), HP_MAX);
                dH[k] = (float)hcc - Hu;
                dW[k] = (float)wcc - Wu;
                v00[k] = fetch_padded(img, hfc, wfc);
                v01[k] = fetch_padded(img, hfc, wcc);
                v10[k] = fetch_padded(img, hcc, wfc);
                v11[k] = fetch_padded(img, hcc, wcc);
            }
        }

        // phase 2: pure-FMA combine + coalesced scalar stores
        #pragma unroll
        for (int k = 0; k < RPT; k++) {
            float eH = 1.0f - dH[k];
            float eW = 1.0f - dW[k];
            float a = fmaf(eW, v01[k], dW[k] * v00[k]);
            float b = fmaf(eW, v11[k], dW[k] * v10[k]);
            out[gbase + (k << 12)] = fmaf(eH, b, dH[k] * a);
        }
    }
}

extern "C" void kernel_launch(void* const* d_in, const int* in_sizes, int n_in,
                              void* d_out, int out_size) {
    const float* img   = (const float*)d_in[0];
    const float* flowH = (const float*)d_in[1];
    const float* flowW = (const float*)d_in[1] + (size_t)H_DIM * W_DIM;
    float* out = (float*)d_out;

    dim3 grid(W_DIM / 256, H_DIM / (RPT * NITER));   // 16 x 256 = 4096 blocks
    dense_warp_kernel<<<grid, 256>>>(img, flowH, flowW, out);
}

// round 14
// speedup vs baseline: 1.0365x; 1.0365x over previous
#include <cuda_runtime.h>
#include <cstdint>

// Dense 2D spatial transformer (bilinear warp, zero-padded border).
// R12: 3-stage software pipeline over vertical strips (RPT=2 rows/stage,
// NITER=8 stages -> block = 256 cols x 16 rows):
//   iter g:  flow load (g+2)  |  gather issue (g+1)  |  combine+store (g)
// Both memory latencies (flow, gathers) are hidden one iteration deep.
// Warp gather footprint stays 32 consecutive columns (R9 result).
//
// Reference semantics (padded coords in [0,4097], zero border):
//   H_up = flow_h + h + 1 ; W_up = flow_w + w + 1
//   hf = clip(floor(H_up),0,4097); hc = clip(hf+1,0,4097); same for w
//   dH = hc - H_up; dW = wc - W_up   (weights from CLIPPED coords)
//   out = v00*dW*dH + v10*dW*(1-dH) + v01*(1-dW)*dH + v11*(1-dW)*(1-dH)

#define H_DIM 4096
#define W_DIM 4096
#define HP_MAX 4097
#define RPT 2      // rows per pipeline stage
#define NITER 8    // stages per block -> 16 rows per block

__device__ __forceinline__ float fetch_padded(const float* __restrict__ img, int h, int w) {
    bool in = ((unsigned)(h - 1) < (unsigned)H_DIM) & ((unsigned)(w - 1) < (unsigned)W_DIM);
    int idx = ((h - 1) << 12) + (w - 1);
    return in ? __ldg(img + idx) : 0.0f;
}

__global__ void __launch_bounds__(256, 4)
dense_warp_kernel(const float* __restrict__ img,
                  const float* __restrict__ flowH,
                  const float* __restrict__ flowW,
                  float* __restrict__ out) {
    const int w  = (blockIdx.x << 8) + threadIdx.x;
    const int h0 = blockIdx.y * (RPT * NITER);
    const int base0 = (h0 << 12) + w;
    const float wp1 = (float)(w + 1);

    float fh[2][RPT], fw[2][RPT];
    float v00[2][RPT], v01[2][RPT], v10[2][RPT], v11[2][RPT];
    float dH[2][RPT], dW[2][RPT];

    // ---- prologue: flow for groups 0 and 1 ----
    #pragma unroll
    for (int k = 0; k < RPT; k++) {
        fh[0][k] = __ldg(flowH + base0 + (k << 12));
        fw[0][k] = __ldg(flowW + base0 + (k << 12));
    }
    #pragma unroll
    for (int k = 0; k < RPT; k++) {
        fh[1][k] = __ldg(flowH + base0 + ((RPT + k) << 12));
        fw[1][k] = __ldg(flowW + base0 + ((RPT + k) << 12));
    }

    // gather-issue for a group into buffer slot `s`
    auto gather_stage = [&](int s, int g) {
        const float hp1 = (float)(h0 + g * RPT + 1);
        #pragma unroll
        for (int k = 0; k < RPT; k++) {
            float Hu = fh[s][k] + hp1 + (float)k;
            float Wu = fw[s][k] + wp1;

            float fhf = floorf(Hu);
            float fwf = floorf(Wu);
            int hf = (int)fhf;
            int wf = (int)fwf;

            if (((unsigned)(hf - 1) <= 4094u) & ((unsigned)(wf - 1) <= 4094u)) {
                dH[s][k] = (fhf + 1.0f) - Hu;
                dW[s][k] = (fwf + 1.0f) - Wu;
                int idx = (hf << 12) + wf - (W_DIM + 1);   // (hf-1)*4096 + (wf-1)
                v00[s][k] = __ldg(img + idx);
                v01[s][k] = __ldg(img + idx + 1);
                v10[s][k] = __ldg(img + idx + W_DIM);
                v11[s][k] = __ldg(img + idx + W_DIM + 1);
            } else {
                int hc = hf + 1, wc = wf + 1;
                int hfc = min(max(hf, 0), HP_MAX);
                int hcc = min(max(hc, 0), HP_MAX);
                int wfc = min(max(wf, 0), HP_MAX);
                int wcc = min(max(wc, 0), HP_MAX);
                dH[s][k] = (float)hcc - Hu;
                dW[s][k] = (float)wcc - Wu;
                v00[s][k] = fetch_padded(img, hfc, wfc);
                v01[s][k] = fetch_padded(img, hfc, wcc);
                v10[s][k] = fetch_padded(img, hcc, wfc);
                v11[s][k] = fetch_padded(img, hcc, wcc);
            }
        }
    };

    // prologue: gathers for group 0 (slot 0)
    gather_stage(0, 0);

    // ---- main loop ----
    #pragma unroll
    for (int g = 0; g < NITER; g++) {
        const int cur = g & 1;
        const int nxt = cur ^ 1;

        // stage A: flow load for group g+2 into slot cur (consumed last iter)
        if (g + 2 < NITER) {
            const int nbase = base0 + (((g + 2) * RPT) << 12);
            #pragma unroll
            for (int k = 0; k < RPT; k++) {
                fh[cur][k] = __ldg(flowH + nbase + (k << 12));
                fw[cur][k] = __ldg(flowW + nbase + (k << 12));
            }
        }

        // stage B: gather issue for group g+1 (slot nxt; flow loaded at iter g-1)
        if (g + 1 < NITER) {
            gather_stage(nxt, g + 1);
        }

        // stage C: combine + store group g (gathers issued at iter g-1)
        const int gbase = base0 + ((g * RPT) << 12);
        #pragma unroll
        for (int k = 0; k < RPT; k++) {
            float eH = 1.0f - dH[cur][k];
            float eW = 1.0f - dW[cur][k];
            float a = fmaf(eW, v01[cur][k], dW[cur][k] * v00[cur][k]);
            float b = fmaf(eW, v11[cur][k], dW[cur][k] * v10[cur][k]);
            out[gbase + (k << 12)] = fmaf(eH, b, dH[cur][k] * a);
        }
    }
}

extern "C" void kernel_launch(void* const* d_in, const int* in_sizes, int n_in,
                              void* d_out, int out_size) {
    const float* img   = (const float*)d_in[0];
    const float* flowH = (const float*)d_in[1];
    const float* flowW = (const float*)d_in[1] + (size_t)H_DIM * W_DIM;
    float* out = (float*)d_out;

    dim3 grid(W_DIM / 256, H_DIM / (RPT * NITER));   // 16 x 256 = 4096 blocks
    dense_warp_kernel<<<grid, 256>>>(img, flowH, flowW, out);
}